// round 8
// baseline (speedup 1.0000x reference)
#include <cuda_runtime.h>
#include <cuda_bf16.h>
#include <float.h>
#include <stdint.h>

#define BSZ 16
#define NP  4096
#define ND  256
#define NC  512
#define MARGIN 1e-3f

#define NMT  32                 // m-tiles per batch == warp size (by design)
#define MAXC 4
#define LDT  72                 // smem chunk pitch (64 + 8 pad) in bf16 elems

// ---- scratch (static device memory) ----
__device__ float g_smax[BSZ * NMT * NC];
__device__ int   g_scnt[BSZ * NMT * NC];
__device__ float g_cval[(size_t)BSZ * NMT * NC * MAXC];
__device__ int   g_cpos[(size_t)BSZ * NMT * NC * MAXC];

// ---------------------------------------------------------------------------
__global__ void zero_kernel(float4* __restrict__ out, int n4) {
    int i = blockIdx.x * blockDim.x + threadIdx.x;
    float4 z = make_float4(0.f, 0.f, 0.f, 0.f);
    for (; i < n4; i += gridDim.x * blockDim.x) out[i] = z;
}

// ---------------------------------------------------------------------------
// bf16 tensor GEMM with FUSED fp32->bf16 conversion on the load path and
// fused per-channel argmax/candidate epilogue.
// Grid (nt=4, mt=32, b=16), 256 threads, warps 4(m) x 2(n), warp tile 32x64.
// K staged in 4 chunks of 64, register-double-buffered LDG->CVT->STS.
// ---------------------------------------------------------------------------
__global__ __launch_bounds__(256, 1)
void gemm_kernel(const float* __restrict__ x, const float* __restrict__ kern) {
    extern __shared__ __nv_bfloat16 sm[];
    __nv_bfloat16* As = sm;                    // [2][128*LDT]
    __nv_bfloat16* Bs = sm + 2 * 128 * LDT;    // [2][128*LDT]

    const int b = blockIdx.z, mt = blockIdx.y, nt = blockIdx.x;
    const int tid = threadIdx.x, lane = tid & 31, warp = tid >> 5;
    const int wm = warp & 3, wn = warp >> 2;   // 4 x 2 warp grid

    const float* Agf = x    + ((size_t)b * NP + mt * 128) * ND;
    const float* Bgf = kern + (size_t)nt * 128 * ND;

    float acc[2][8][4];
    #pragma unroll
    for (int i = 0; i < 2; ++i)
        #pragma unroll
        for (int j = 0; j < 8; ++j)
            #pragma unroll
            for (int q = 0; q < 4; ++q) acc[i][j][q] = 0.f;

    float4 aR[8], bR[8];   // fp32 staging registers for the next chunk

    auto load_regs = [&](int kc) {
        #pragma unroll
        for (int it = 0; it < 8; ++it) {
            int idx = it * 256 + tid;
            int r = idx >> 4, c4 = idx & 15;     // row, float4 within 64 floats
            aR[it] = ((const float4*)(Agf + (size_t)r * ND + kc * 64))[c4];
            bR[it] = ((const float4*)(Bgf + (size_t)r * ND + kc * 64))[c4];
        }
    };

    auto sts_stage = [&](int st) {
        int base = st * 128 * LDT;
        #pragma unroll
        for (int it = 0; it < 8; ++it) {
            int idx = it * 256 + tid;
            int r = idx >> 4, c4 = idx & 15;
            __nv_bfloat162 a0 = __floats2bfloat162_rn(aR[it].x, aR[it].y);
            __nv_bfloat162 a1 = __floats2bfloat162_rn(aR[it].z, aR[it].w);
            uint2 ua; ua.x = *(uint32_t*)&a0; ua.y = *(uint32_t*)&a1;
            *(uint2*)&As[base + r * LDT + c4 * 4] = ua;
            __nv_bfloat162 b0 = __floats2bfloat162_rn(bR[it].x, bR[it].y);
            __nv_bfloat162 b1 = __floats2bfloat162_rn(bR[it].z, bR[it].w);
            uint2 ub; ub.x = *(uint32_t*)&b0; ub.y = *(uint32_t*)&b1;
            *(uint2*)&Bs[base + r * LDT + c4 * 4] = ub;
        }
    };

    load_regs(0);
    sts_stage(0);
    load_regs(1);
    __syncthreads();

    const int lm = lane & 15, lk = (lane >> 4) * 8;

    #pragma unroll
    for (int kc = 0; kc < 4; ++kc) {
        const int st = kc & 1;
        if (kc < 3) sts_stage(st ^ 1);     // chunk kc+1 (stage safe: readers of
                                           // it finished before last sync)
        if (kc < 2) load_regs(kc + 2);     // prefetch chunk kc+2 into regs

        const __nv_bfloat16* Ab = As + st * 128 * LDT + wm * 32 * LDT;
        const __nv_bfloat16* Bb = Bs + st * 128 * LDT + wn * 64 * LDT;

        #pragma unroll
        for (int ks = 0; ks < 4; ++ks) {
            uint32_t af[2][4], bfv[4][4];
            #pragma unroll
            for (int i = 0; i < 2; ++i) {
                uint32_t addr = (uint32_t)__cvta_generic_to_shared(
                    Ab + (i * 16 + lm) * LDT + ks * 16 + lk);
                asm volatile("ldmatrix.sync.aligned.m8n8.x4.shared.b16 {%0,%1,%2,%3}, [%4];"
                    : "=r"(af[i][0]), "=r"(af[i][1]), "=r"(af[i][2]), "=r"(af[i][3])
                    : "r"(addr));
            }
            #pragma unroll
            for (int jj = 0; jj < 4; ++jj) {
                uint32_t addr = (uint32_t)__cvta_generic_to_shared(
                    Bb + (jj * 16 + lm) * LDT + ks * 16 + lk);
                asm volatile("ldmatrix.sync.aligned.m8n8.x4.shared.b16 {%0,%1,%2,%3}, [%4];"
                    : "=r"(bfv[jj][0]), "=r"(bfv[jj][1]), "=r"(bfv[jj][2]), "=r"(bfv[jj][3])
                    : "r"(addr));
            }
            #pragma unroll
            for (int i = 0; i < 2; ++i)
                #pragma unroll
                for (int j = 0; j < 8; ++j) {
                    uint32_t b0 = bfv[j >> 1][(j & 1)];
                    uint32_t b1 = bfv[j >> 1][(j & 1) + 2];
                    asm volatile(
                        "mma.sync.aligned.m16n8k16.row.col.f32.bf16.bf16.f32 "
                        "{%0,%1,%2,%3}, {%4,%5,%6,%7}, {%8,%9}, {%0,%1,%2,%3};"
                        : "+f"(acc[i][j][0]), "+f"(acc[i][j][1]),
                          "+f"(acc[i][j][2]), "+f"(acc[i][j][3])
                        : "r"(af[i][0]), "r"(af[i][1]), "r"(af[i][2]), "r"(af[i][3]),
                          "r"(b0), "r"(b1));
                }
        }
        __syncthreads();
    }

    // ================= fused epilogue: per-channel block argmax ==============
    float* sval = (float*)sm;                    // [128][33]
    int*   sidx = (int*)(sval + 128 * 33);       // [128][33]
    float* sbm  = (float*)(sidx + 128 * 33);     // [128]
    int*   sbi  = (int*)(sbm + 128);             // [128]
    int*   scnt = (int*)(sbi + 128);             // [128]
    float* scv  = (float*)(scnt + 128);          // [128][MAXC]
    int*   scp  = (int*)(scv + 128 * MAXC);      // [128][MAXC]

    const int gq = lane >> 2, q2 = (lane & 3) * 2;
    const int rowgrp = wm * 8 + gq;              // 32 partials per channel
    const int pbase  = mt * 128 + wm * 32;

    // pass 1: per-thread partial (max, idx) per channel
    #pragma unroll
    for (int j = 0; j < 8; ++j)
        #pragma unroll
        for (int e = 0; e < 2; ++e) {
            int ch = wn * 64 + j * 8 + q2 + e;
            float m = -FLT_MAX; int mi = 0;
            #pragma unroll
            for (int i = 0; i < 2; ++i) {
                int p0 = pbase + i * 16 + gq;
                float v0 = acc[i][j][e];
                float v1 = acc[i][j][e + 2];
                if (v0 > m) { m = v0; mi = p0; }
                if (v1 > m) { m = v1; mi = p0 + 8; }
            }
            sval[ch * 33 + rowgrp] = m;
            sidx[ch * 33 + rowgrp] = mi;
        }
    __syncthreads();

    // reduce 32 partials; slot 0 = the block max itself (guaranteed kept)
    if (tid < 128) {
        float bv = -FLT_MAX; int bi = 0;
        #pragma unroll
        for (int r = 0; r < 32; ++r) {
            float v  = sval[tid * 33 + r];
            int   ii = sidx[tid * 33 + r];
            if (v > bv || (v == bv && ii < bi)) { bv = v; bi = ii; }
        }
        sbm[tid]  = bv;
        sbi[tid]  = bi;
        scnt[tid] = 1;
        scv[tid * MAXC] = bv;
        scp[tid * MAXC] = bi;
    }
    __syncthreads();

    // pass 2: collect other candidates within MARGIN of block max
    #pragma unroll
    for (int j = 0; j < 8; ++j)
        #pragma unroll
        for (int e = 0; e < 2; ++e) {
            int ch = wn * 64 + j * 8 + q2 + e;
            float thr = sbm[ch] - MARGIN;
            int   bi  = sbi[ch];
            #pragma unroll
            for (int i = 0; i < 2; ++i) {
                int p0 = pbase + i * 16 + gq;
                float v0 = acc[i][j][e];
                float v1 = acc[i][j][e + 2];
                if (v0 > thr && p0 != bi) {
                    int slot = atomicAdd(&scnt[ch], 1);
                    if (slot < MAXC) { scv[ch * MAXC + slot] = v0; scp[ch * MAXC + slot] = p0; }
                }
                if (v1 > thr && (p0 + 8) != bi) {
                    int slot = atomicAdd(&scnt[ch], 1);
                    if (slot < MAXC) { scv[ch * MAXC + slot] = v1; scp[ch * MAXC + slot] = p0 + 8; }
                }
            }
        }
    __syncthreads();

    if (tid < 128) {
        int o = (b * NMT + mt) * NC + nt * 128 + tid;
        int n = min(scnt[tid], MAXC);
        g_smax[o] = sbm[tid];
        g_scnt[o] = n;
        for (int i = 0; i < n; ++i) {
            g_cval[(size_t)o * MAXC + i] = scv[tid * MAXC + i];
            g_cpos[(size_t)o * MAXC + i] = scp[tid * MAXC + i];
        }
    }
}

// ---------------------------------------------------------------------------
// Merge + scatter: warp per (b,c); lane l owns m-tile l. Fast path: if exactly
// one candidate survives the global margin and gmax > MARGIN, it is the exact
// winner (bf16 error << MARGIN) and its true score is provably positive -> no
// rescore loads at all. Otherwise exact fp32 warp-cooperative rescore.
// ---------------------------------------------------------------------------
__global__ __launch_bounds__(256)
void merge_scatter_kernel(const float* __restrict__ x,
                          const float* __restrict__ kern,
                          float* __restrict__ out) {
    int task = blockIdx.x * 8 + (threadIdx.x >> 5);
    int lane = threadIdx.x & 31;
    int b = task >> 9, c = task & (NC - 1);

    const int o = (b * NMT + lane) * NC + c;
    float tmax = g_smax[o];
    int   cnt  = g_scnt[o];

    float gmax = tmax;
    #pragma unroll
    for (int off = 16; off > 0; off >>= 1)
        gmax = fmaxf(gmax, __shfl_xor_sync(0xffffffffu, gmax, off));
    const float thr = gmax - MARGIN;

    // load candidates, ballot survivors
    float cvs[MAXC]; int cps[MAXC]; unsigned masks[MAXC]; int total = 0;
    #pragma unroll
    for (int i = 0; i < MAXC; ++i) {
        bool act = (i < cnt);
        cvs[i] = act ? g_cval[(size_t)o * MAXC + i] : -FLT_MAX;
        cps[i] = act ? g_cpos[(size_t)o * MAXC + i] : 0;
        masks[i] = __ballot_sync(0xffffffffu, act && cvs[i] > thr);
        total += __popc(masks[i]);
    }

    const float* kr = kern + (size_t)c * ND;
    float4 k4a = *(const float4*)&kr[lane * 8];
    float4 k4b = *(const float4*)&kr[lane * 8 + 4];

    int bestp;
    if (total == 1 && gmax > MARGIN) {
        // unique winner by margin; sign certain
        bestp = 0;
        #pragma unroll
        for (int i = 0; i < MAXC; ++i)
            if (masks[i]) {
                int l = __ffs(masks[i]) - 1;
                bestp = __shfl_sync(0xffffffffu, cps[i], l);
            }
    } else {
        float bestv = -FLT_MAX; bestp = 0x7fffffff; bool have = false;
        #pragma unroll
        for (int i = 0; i < MAXC; ++i) {
            unsigned mask = masks[i];
            while (mask) {
                int l = __ffs(mask) - 1; mask &= mask - 1;
                int p = __shfl_sync(0xffffffffu, cps[i], l);
                const float* xr = x + ((size_t)b * NP + p) * ND + lane * 8;
                float4 xa = *(const float4*)xr;
                float4 xb = *(const float4*)(xr + 4);
                float sum = xa.x * k4a.x + xa.y * k4a.y + xa.z * k4a.z + xa.w * k4a.w
                          + xb.x * k4b.x + xb.y * k4b.y + xb.z * k4b.z + xb.w * k4b.w;
                #pragma unroll
                for (int off = 16; off > 0; off >>= 1)
                    sum += __shfl_xor_sync(0xffffffffu, sum, off);
                if (!have || sum > bestv || (sum == bestv && p < bestp)) {
                    bestv = sum; bestp = p; have = true;
                }
            }
        }
        if (bestv <= 0.f) bestp = 0;   // all-ReLU-zero => argmax = 0
    }

    float* dst = out + ((size_t)b * NP + bestp) * ND + lane * 8;
    atomicAdd(&dst[0], k4a.x); atomicAdd(&dst[1], k4a.y);
    atomicAdd(&dst[2], k4a.z); atomicAdd(&dst[3], k4a.w);
    atomicAdd(&dst[4], k4b.x); atomicAdd(&dst[5], k4b.y);
    atomicAdd(&dst[6], k4b.z); atomicAdd(&dst[7], k4b.w);
}

// ---------------------------------------------------------------------------
extern "C" void kernel_launch(void* const* d_in, const int* in_sizes, int n_in,
                              void* d_out, int out_size) {
    const float* x    = (const float*)d_in[0];
    const float* kern = (const float*)d_in[1];
    float*       out  = (float*)d_out;

    zero_kernel<<<4096, 256>>>((float4*)out, BSZ * NP * ND / 4);

    size_t smem = 2 * 2 * 128 * LDT * sizeof(__nv_bfloat16);   // 73,728 B
    cudaFuncSetAttribute(gemm_kernel,
                         cudaFuncAttributeMaxDynamicSharedMemorySize, (int)smem);
    gemm_kernel<<<dim3(4, NMT, BSZ), 256, smem>>>(x, kern);

    merge_scatter_kernel<<<BSZ * NC / 8, 256>>>(x, kern, out);
}

// round 9
// speedup vs baseline: 1.3222x; 1.3222x over previous
#include <cuda_runtime.h>
#include <cuda_bf16.h>
#include <float.h>
#include <stdint.h>

#define BSZ 16
#define NP  4096
#define ND  256
#define NC  512
#define MARGIN 1e-3f

#define NMT  32                 // m-tiles per batch == warp size (by design)
#define MAXC 4
#define LDT  72                 // smem chunk pitch (64 + 8 pad) in bf16 elems

// ---- scratch (static device memory) ----
__device__ __nv_bfloat16 g_xbf[(size_t)BSZ * NP * ND];   // 33.5 MB
__device__ __nv_bfloat16 g_kbf[NC * ND];                  // 256 KB
__device__ float g_smax[BSZ * NMT * NC];
__device__ int   g_scnt[BSZ * NMT * NC];
__device__ float g_cval[(size_t)BSZ * NMT * NC * MAXC];
__device__ int   g_cpos[(size_t)BSZ * NMT * NC * MAXC];

// ---------------------------------------------------------------------------
// Fused: zero the output AND convert x/kernels to bf16, one grid-stride pass.
// ---------------------------------------------------------------------------
__global__ void prep_kernel(const float* __restrict__ x,
                            const float* __restrict__ kern,
                            float4* __restrict__ out) {
    const int NZ4 = BSZ * NP * ND / 4;        // zero items
    const int NX4 = BSZ * NP * ND / 4;        // x convert items
    const int NK4 = NC * ND / 4;              // kernel convert items
    const int TOT = NZ4 + NX4 + NK4;
    const float4 z = make_float4(0.f, 0.f, 0.f, 0.f);
    for (int i = blockIdx.x * blockDim.x + threadIdx.x; i < TOT;
         i += gridDim.x * blockDim.x) {
        if (i < NZ4) {
            out[i] = z;
        } else if (i < NZ4 + NX4) {
            int j = i - NZ4;
            float4 v = ((const float4*)x)[j];
            ((__nv_bfloat162*)g_xbf)[j * 2]     = __floats2bfloat162_rn(v.x, v.y);
            ((__nv_bfloat162*)g_xbf)[j * 2 + 1] = __floats2bfloat162_rn(v.z, v.w);
        } else {
            int j = i - NZ4 - NX4;
            float4 v = ((const float4*)kern)[j];
            ((__nv_bfloat162*)g_kbf)[j * 2]     = __floats2bfloat162_rn(v.x, v.y);
            ((__nv_bfloat162*)g_kbf)[j * 2 + 1] = __floats2bfloat162_rn(v.z, v.w);
        }
    }
}

// ---------------------------------------------------------------------------
// bf16 tensor GEMM 128x128 tile + fused argmax epilogue (round-6 known-good).
// ---------------------------------------------------------------------------
__global__ __launch_bounds__(256)
void gemm_kernel() {
    extern __shared__ __nv_bfloat16 sm[];
    __nv_bfloat16* As = sm;                    // [2][128*LDT]
    __nv_bfloat16* Bs = sm + 2 * 128 * LDT;    // [2][128*LDT]

    const int b = blockIdx.z, mt = blockIdx.y, nt = blockIdx.x;
    const int tid = threadIdx.x, lane = tid & 31, warp = tid >> 5;
    const int wm = warp & 1, wn = warp >> 1;

    const __nv_bfloat16* Ag = g_xbf + ((size_t)b * NP + mt * 128) * ND;
    const __nv_bfloat16* Bg = g_kbf + (size_t)nt * 128 * ND;

    float acc[4][4][4];
    #pragma unroll
    for (int i = 0; i < 4; ++i)
        #pragma unroll
        for (int j = 0; j < 4; ++j)
            #pragma unroll
            for (int q = 0; q < 4; ++q) acc[i][j][q] = 0.f;

    auto issue = [&](int kc, int st) {
        int base = st * 128 * LDT;
        #pragma unroll
        for (int it = 0; it < 4; ++it) {
            int i = it * 256 + tid;
            int r = i >> 3, c = (i & 7) * 8;
            uint32_t sa = (uint32_t)__cvta_generic_to_shared(&As[base + r * LDT + c]);
            const __nv_bfloat16* ga = Ag + (size_t)r * ND + kc * 64 + c;
            asm volatile("cp.async.cg.shared.global [%0], [%1], 16;" :: "r"(sa), "l"(ga) : "memory");
            uint32_t sb = (uint32_t)__cvta_generic_to_shared(&Bs[base + r * LDT + c]);
            const __nv_bfloat16* gb = Bg + (size_t)r * ND + kc * 64 + c;
            asm volatile("cp.async.cg.shared.global [%0], [%1], 16;" :: "r"(sb), "l"(gb) : "memory");
        }
        asm volatile("cp.async.commit_group;" ::: "memory");
    };

    issue(0, 0);
    issue(1, 1);

    const int lm = lane & 15, lk = (lane >> 4) * 8;

    #pragma unroll
    for (int kc = 0; kc < 4; ++kc) {
        if (kc < 3) asm volatile("cp.async.wait_group 1;" ::: "memory");
        else        asm volatile("cp.async.wait_group 0;" ::: "memory");
        __syncthreads();

        int st = kc & 1;
        const __nv_bfloat16* Ab = As + st * 128 * LDT + wm * 64 * LDT;
        const __nv_bfloat16* Bb = Bs + st * 128 * LDT + wn * 32 * LDT;

        #pragma unroll
        for (int ks = 0; ks < 4; ++ks) {
            uint32_t af[4][4], bfv[2][4];
            #pragma unroll
            for (int i = 0; i < 4; ++i) {
                uint32_t addr = (uint32_t)__cvta_generic_to_shared(
                    Ab + (i * 16 + lm) * LDT + ks * 16 + lk);
                asm volatile("ldmatrix.sync.aligned.m8n8.x4.shared.b16 {%0,%1,%2,%3}, [%4];"
                    : "=r"(af[i][0]), "=r"(af[i][1]), "=r"(af[i][2]), "=r"(af[i][3])
                    : "r"(addr));
            }
            #pragma unroll
            for (int j = 0; j < 2; ++j) {
                uint32_t addr = (uint32_t)__cvta_generic_to_shared(
                    Bb + (j * 16 + lm) * LDT + ks * 16 + lk);
                asm volatile("ldmatrix.sync.aligned.m8n8.x4.shared.b16 {%0,%1,%2,%3}, [%4];"
                    : "=r"(bfv[j][0]), "=r"(bfv[j][1]), "=r"(bfv[j][2]), "=r"(bfv[j][3])
                    : "r"(addr));
            }
            #pragma unroll
            for (int i = 0; i < 4; ++i)
                #pragma unroll
                for (int j = 0; j < 4; ++j) {
                    uint32_t b0 = bfv[j >> 1][(j & 1)];
                    uint32_t b1 = bfv[j >> 1][(j & 1) + 2];
                    asm volatile(
                        "mma.sync.aligned.m16n8k16.row.col.f32.bf16.bf16.f32 "
                        "{%0,%1,%2,%3}, {%4,%5,%6,%7}, {%8,%9}, {%0,%1,%2,%3};"
                        : "+f"(acc[i][j][0]), "+f"(acc[i][j][1]),
                          "+f"(acc[i][j][2]), "+f"(acc[i][j][3])
                        : "r"(af[i][0]), "r"(af[i][1]), "r"(af[i][2]), "r"(af[i][3]),
                          "r"(b0), "r"(b1));
                }
        }
        __syncthreads();
        if (kc + 2 < 4) issue(kc + 2, st);
    }

    // ================= fused epilogue: per-channel block argmax ==============
    float* sval = (float*)sm;                    // [128][17]
    int*   sidx = (int*)(sval + 128 * 17);       // [128][17]
    float* sbm  = (float*)(sidx + 128 * 17);     // [128]
    int*   sbi  = (int*)(sbm + 128);             // [128]
    int*   scnt = (int*)(sbi + 128);             // [128]
    float* scv  = (float*)(scnt + 128);          // [128][MAXC]
    int*   scp  = (int*)(scv + 128 * MAXC);      // [128][MAXC]

    const int gq = lane >> 2, q2 = (lane & 3) * 2;
    const int rowgrp = wm * 8 + gq;
    const int pbase  = mt * 128 + wm * 64;

    #pragma unroll
    for (int j = 0; j < 4; ++j)
        #pragma unroll
        for (int e = 0; e < 2; ++e) {
            int ch = wn * 32 + j * 8 + q2 + e;
            float m = -FLT_MAX; int mi = 0;
            #pragma unroll
            for (int i = 0; i < 4; ++i) {
                int p0 = pbase + i * 16 + gq;
                float v0 = acc[i][j][e];
                float v1 = acc[i][j][e + 2];
                if (v0 > m) { m = v0; mi = p0; }
                if (v1 > m) { m = v1; mi = p0 + 8; }
            }
            sval[ch * 17 + rowgrp] = m;
            sidx[ch * 17 + rowgrp] = mi;
        }
    __syncthreads();

    if (tid < 128) {
        float bv = -FLT_MAX; int bi = 0;
        #pragma unroll
        for (int r = 0; r < 16; ++r) {
            float v  = sval[tid * 17 + r];
            int   ii = sidx[tid * 17 + r];
            if (v > bv || (v == bv && ii < bi)) { bv = v; bi = ii; }
        }
        sbm[tid]  = bv;
        sbi[tid]  = bi;
        scnt[tid] = 1;
        scv[tid * MAXC] = bv;
        scp[tid * MAXC] = bi;
    }
    __syncthreads();

    #pragma unroll
    for (int j = 0; j < 4; ++j)
        #pragma unroll
        for (int e = 0; e < 2; ++e) {
            int ch = wn * 32 + j * 8 + q2 + e;
            float thr = sbm[ch] - MARGIN;
            int   bi  = sbi[ch];
            #pragma unroll
            for (int i = 0; i < 4; ++i) {
                int p0 = pbase + i * 16 + gq;
                float v0 = acc[i][j][e];
                float v1 = acc[i][j][e + 2];
                if (v0 > thr && p0 != bi) {
                    int slot = atomicAdd(&scnt[ch], 1);
                    if (slot < MAXC) { scv[ch * MAXC + slot] = v0; scp[ch * MAXC + slot] = p0; }
                }
                if (v1 > thr && (p0 + 8) != bi) {
                    int slot = atomicAdd(&scnt[ch], 1);
                    if (slot < MAXC) { scv[ch * MAXC + slot] = v1; scp[ch * MAXC + slot] = p0 + 8; }
                }
            }
        }
    __syncthreads();

    if (tid < 128) {
        int o = (b * NMT + mt) * NC + nt * 128 + tid;
        int n = min(scnt[tid], MAXC);
        g_smax[o] = sbm[tid];
        g_scnt[o] = n;
        for (int i = 0; i < n; ++i) {
            g_cval[(size_t)o * MAXC + i] = scv[tid * MAXC + i];
            g_cpos[(size_t)o * MAXC + i] = scp[tid * MAXC + i];
        }
    }
}

// ---------------------------------------------------------------------------
// Merge + scatter: warp per (b,c); lane l owns m-tile l. Fast path: unique
// margin-survivor with gmax > MARGIN wins without any rescore loads.
// ---------------------------------------------------------------------------
__global__ __launch_bounds__(256)
void merge_scatter_kernel(const float* __restrict__ x,
                          const float* __restrict__ kern,
                          float* __restrict__ out) {
    int task = blockIdx.x * 8 + (threadIdx.x >> 5);
    int lane = threadIdx.x & 31;
    int b = task >> 9, c = task & (NC - 1);

    const int o = (b * NMT + lane) * NC + c;
    float tmax = g_smax[o];
    int   cnt  = g_scnt[o];

    float gmax = tmax;
    #pragma unroll
    for (int off = 16; off > 0; off >>= 1)
        gmax = fmaxf(gmax, __shfl_xor_sync(0xffffffffu, gmax, off));
    const float thr = gmax - MARGIN;

    float cvs[MAXC]; int cps[MAXC]; unsigned masks[MAXC]; int total = 0;
    #pragma unroll
    for (int i = 0; i < MAXC; ++i) {
        bool act = (i < cnt);
        cvs[i] = act ? g_cval[(size_t)o * MAXC + i] : -FLT_MAX;
        cps[i] = act ? g_cpos[(size_t)o * MAXC + i] : 0;
        masks[i] = __ballot_sync(0xffffffffu, act && cvs[i] > thr);
        total += __popc(masks[i]);
    }

    const float* kr = kern + (size_t)c * ND;
    float4 k4a = *(const float4*)&kr[lane * 8];
    float4 k4b = *(const float4*)&kr[lane * 8 + 4];

    int bestp;
    if (total == 1 && gmax > MARGIN) {
        bestp = 0;
        #pragma unroll
        for (int i = 0; i < MAXC; ++i)
            if (masks[i]) {
                int l = __ffs(masks[i]) - 1;
                bestp = __shfl_sync(0xffffffffu, cps[i], l);
            }
    } else {
        float bestv = -FLT_MAX; bestp = 0x7fffffff; bool have = false;
        #pragma unroll
        for (int i = 0; i < MAXC; ++i) {
            unsigned mask = masks[i];
            while (mask) {
                int l = __ffs(mask) - 1; mask &= mask - 1;
                int p = __shfl_sync(0xffffffffu, cps[i], l);
                const float* xr = x + ((size_t)b * NP + p) * ND + lane * 8;
                float4 xa = *(const float4*)xr;
                float4 xb = *(const float4*)(xr + 4);
                float sum = xa.x * k4a.x + xa.y * k4a.y + xa.z * k4a.z + xa.w * k4a.w
                          + xb.x * k4b.x + xb.y * k4b.y + xb.z * k4b.z + xb.w * k4b.w;
                #pragma unroll
                for (int off = 16; off > 0; off >>= 1)
                    sum += __shfl_xor_sync(0xffffffffu, sum, off);
                if (!have || sum > bestv || (sum == bestv && p < bestp)) {
                    bestv = sum; bestp = p; have = true;
                }
            }
        }
        if (bestv <= 0.f) bestp = 0;   // all-ReLU-zero => argmax = 0
    }

    float* dst = out + ((size_t)b * NP + bestp) * ND + lane * 8;
    atomicAdd(&dst[0], k4a.x); atomicAdd(&dst[1], k4a.y);
    atomicAdd(&dst[2], k4a.z); atomicAdd(&dst[3], k4a.w);
    atomicAdd(&dst[4], k4b.x); atomicAdd(&dst[5], k4b.y);
    atomicAdd(&dst[6], k4b.z); atomicAdd(&dst[7], k4b.w);
}

// ---------------------------------------------------------------------------
extern "C" void kernel_launch(void* const* d_in, const int* in_sizes, int n_in,
                              void* d_out, int out_size) {
    const float* x    = (const float*)d_in[0];
    const float* kern = (const float*)d_in[1];
    float*       out  = (float*)d_out;

    prep_kernel<<<8448, 256>>>(x, kern, (float4*)out);

    size_t smem = 2 * 2 * 128 * LDT * sizeof(__nv_bfloat16);   // 73,728 B
    cudaFuncSetAttribute(gemm_kernel,
                         cudaFuncAttributeMaxDynamicSharedMemorySize, (int)smem);
    gemm_kernel<<<dim3(4, NMT, BSZ), 256, smem>>>();

    merge_scatter_kernel<<<BSZ * NC / 8, 256>>>(x, kern, out);
}